// round 10
// baseline (speedup 1.0000x reference)
#include <cuda_runtime.h>
#include <cuda_bf16.h>
#include <cstdint>

#define NROWS 8192
#define DIM   1024
#define SCALE_T 14.4269504088896341f   // (1/T)*log2(e)
#define LN2F 0.69314718055994531f

// ---------------- scratch ----------------
__device__ __nv_bfloat16 g_imn[(size_t)NROWS * DIM];   // normalized * SCALE_T
__device__ __nv_bfloat16 g_capn[(size_t)NROWS * DIM];  // normalized
__device__ float g_rowsum[NROWS];
__device__ float g_colsum[NROWS];
__device__ float g_diag[NROWS];                        // t_ii (exp2-domain logits)
__device__ float g_parta[32];
__device__ float g_partd[32];

// ---------------- helpers ----------------
__device__ __forceinline__ uint32_t smem_u32(const void* p) {
    uint32_t a;
    asm("{ .reg .u64 t; cvta.to.shared.u64 t, %1; cvt.u32.u64 %0, t; }" : "=r"(a) : "l"(p));
    return a;
}
__device__ __forceinline__ uint64_t gmem_u64(const void* p) {
    uint64_t a;
    asm("cvta.to.global.u64 %0, %1;" : "=l"(a) : "l"(p));
    return a;
}
#define SW128(o) ((o) ^ (((o) >> 3) & 0x70))

// ---------------- 1) prep: normalize both rows + diag + zero accumulators ----------------
__global__ void prep_kernel(const float* __restrict__ im,
                            const float* __restrict__ cap) {
    int row = blockIdx.x;
    int tid = threadIdx.x;
    const float4* a4 = reinterpret_cast<const float4*>(im + (size_t)row * DIM);
    const float4* b4 = reinterpret_cast<const float4*>(cap + (size_t)row * DIM);
    float4 va = a4[tid], vb = b4[tid];
    float sa = va.x * va.x + va.y * va.y + va.z * va.z + va.w * va.w;
    float sb = vb.x * vb.x + vb.y * vb.y + vb.z * vb.z + vb.w * vb.w;
    float sd = va.x * vb.x + va.y * vb.y + va.z * vb.z + va.w * vb.w;
    #pragma unroll
    for (int o = 16; o; o >>= 1) {
        sa += __shfl_xor_sync(0xffffffffu, sa, o);
        sb += __shfl_xor_sync(0xffffffffu, sb, o);
        sd += __shfl_xor_sync(0xffffffffu, sd, o);
    }
    __shared__ float wsa[8], wsb[8], wsd[8];
    if ((tid & 31) == 0) { wsa[tid >> 5] = sa; wsb[tid >> 5] = sb; wsd[tid >> 5] = sd; }
    __syncthreads();
    float ta = 0.f, tb = 0.f, td = 0.f;
    #pragma unroll
    for (int i = 0; i < 8; i++) { ta += wsa[i]; tb += wsb[i]; td += wsd[i]; }

    float ra = rsqrtf(ta), rb = rsqrtf(tb);
    float inva = ra * SCALE_T;
    __nv_bfloat162* dA = reinterpret_cast<__nv_bfloat162*>(g_imn + (size_t)row * DIM);
    __nv_bfloat162* dB = reinterpret_cast<__nv_bfloat162*>(g_capn + (size_t)row * DIM);
    dA[tid * 2 + 0] = __floats2bfloat162_rn(va.x * inva, va.y * inva);
    dA[tid * 2 + 1] = __floats2bfloat162_rn(va.z * inva, va.w * inva);
    dB[tid * 2 + 0] = __floats2bfloat162_rn(vb.x * rb, vb.y * rb);
    dB[tid * 2 + 1] = __floats2bfloat162_rn(vb.z * rb, vb.w * rb);

    if (tid == 0) {
        g_diag[row] = td * ra * rb * SCALE_T;  // t_ii in exp2 domain (fp32 exact)
        g_rowsum[row] = 0.f;
        g_colsum[row] = 0.f;
    }
}

// ---------------- 2) persistent bf16 mma.sync GEMM ----------------
// CTA tile 128x128, BK=64, continuous 3-stage cp.async ring across ~14 tiles/CTA.
// 8 warps = 2(M) x 4(N), warp tile 64x32.
#define BM 128
#define BN 128
#define STAGE_BYTES 32768                 // A 16KB + B 16KB
#define DYN_BYTES (3 * STAGE_BYTES + 1024)
#define GRID_P 296                        // 2 CTA/SM * 148 SM
#define NTILES_TOTAL 4096                 // 64 x 64 tiles

extern __shared__ char dynsmem[];

__device__ __forceinline__ void issue_chunk(int g, int bid, uint32_t sbase,
                                            uint64_t gAbase, uint64_t gBbase, int tid) {
    int tile = bid + (g >> 4) * GRID_P;
    int rb = (tile >> 6) * BM;            // row tile
    int cb = (tile & 63) * BN;            // col tile
    uint32_t sStage = sbase + (uint32_t)(g % 3) * STAGE_BYTES;
    uint32_t k0b = (uint32_t)(g & 15) * 128;
    uint64_t gA = gAbase + (uint64_t)rb * (DIM * 2);
    uint64_t gB = gBbase + (uint64_t)cb * (DIM * 2);
    #pragma unroll
    for (int q = 0; q < 4; q++) {
        int chunk = tid + q * 256;
        int row = chunk >> 3, kc = chunk & 7;
        uint32_t soff = SW128(row * 128 + kc * 16);
        uint64_t goff = (uint64_t)row * (DIM * 2) + k0b + kc * 16;
        asm volatile("cp.async.cg.shared.global [%0], [%1], 16;"
                     :: "r"(sStage + soff), "l"(gA + goff) : "memory");
        asm volatile("cp.async.cg.shared.global [%0], [%1], 16;"
                     :: "r"(sStage + 16384 + soff), "l"(gB + goff) : "memory");
    }
}

__global__ void __launch_bounds__(256, 2) gemm_kernel() {
    const int tid = threadIdx.x, wid = tid >> 5, lane = tid & 31;
    const int warpM = wid >> 2;           // 0..1 -> 64-row slab
    const int warpN = wid & 3;            // 0..3 -> 32-col slab
    const int bid = blockIdx.x;
    const int ntiles = (NTILES_TOTAL - bid + (GRID_P - 1)) / GRID_P;
    const int totalChunks = ntiles * 16;

    __shared__ float rowsum_s[BM];
    __shared__ float colsum_s[BN];
    if (tid < BM) { rowsum_s[tid] = 0.f; colsum_s[tid] = 0.f; }

    uint32_t raw = smem_u32(dynsmem);
    uint32_t sbase = (raw + 1023u) & ~1023u;

    const uint64_t gAbase = gmem_u64(g_imn);
    const uint64_t gBbase = gmem_u64(g_capn);

    issue_chunk(0, bid, sbase, gAbase, gBbase, tid);
    asm volatile("cp.async.commit_group;" ::: "memory");
    issue_chunk(1, bid, sbase, gAbase, gBbase, tid);
    asm volatile("cp.async.commit_group;" ::: "memory");

    float acc[4][4][4];
    #pragma unroll
    for (int i = 0; i < 4; i++)
        #pragma unroll
        for (int j = 0; j < 4; j++)
            #pragma unroll
            for (int r = 0; r < 4; r++) acc[i][j][r] = 0.f;

    // ldmatrix lane geometry
    const int laneRow = lane & 15;
    const uint32_t aXor = (uint32_t)((laneRow & 7) << 4);
    const uint32_t aHi  = (uint32_t)((lane >> 4) * 16);
    const int rowB0 = ((lane >> 4) & 1) * 8 + (lane & 7);
    const uint32_t bXor = (uint32_t)((lane & 7) << 4);
    const uint32_t bHi  = (uint32_t)(((lane >> 3) & 1) * 16);

    for (int g = 0; g < totalChunks; g++) {
        asm volatile("cp.async.wait_group 1;" ::: "memory");
        __syncthreads();
        if (g + 2 < totalChunks)
            issue_chunk(g + 2, bid, sbase, gAbase, gBbase, tid);
        asm volatile("cp.async.commit_group;" ::: "memory");

        const uint32_t sA = sbase + (uint32_t)(g % 3) * STAGE_BYTES;
        const uint32_t sB = sA + 16384;

        #pragma unroll
        for (int kk = 0; kk < 4; kk++) {
            uint32_t a[4][4], b[2][4];
            #pragma unroll
            for (int i = 0; i < 4; i++) {
                uint32_t addr = sA + (uint32_t)(warpM * 64 + i * 16 + laneRow) * 128
                              + (((uint32_t)kk * 32 + aHi) ^ aXor);
                asm volatile("ldmatrix.sync.aligned.m8n8.x4.shared.b16 {%0,%1,%2,%3}, [%4];"
                             : "=r"(a[i][0]), "=r"(a[i][1]), "=r"(a[i][2]), "=r"(a[i][3])
                             : "r"(addr));
            }
            #pragma unroll
            for (int jb = 0; jb < 2; jb++) {
                uint32_t addr = sB + (uint32_t)(warpN * 32 + jb * 16 + rowB0) * 128
                              + (((uint32_t)kk * 32 + bHi) ^ bXor);
                asm volatile("ldmatrix.sync.aligned.m8n8.x4.shared.b16 {%0,%1,%2,%3}, [%4];"
                             : "=r"(b[jb][0]), "=r"(b[jb][1]), "=r"(b[jb][2]), "=r"(b[jb][3])
                             : "r"(addr));
            }
            #pragma unroll
            for (int i = 0; i < 4; i++) {
                #pragma unroll
                for (int j = 0; j < 4; j++) {
                    uint32_t b0 = b[j >> 1][(j & 1) * 2];
                    uint32_t b1 = b[j >> 1][(j & 1) * 2 + 1];
                    asm volatile(
                        "mma.sync.aligned.m16n8k16.row.col.f32.bf16.bf16.f32 "
                        "{%0,%1,%2,%3}, {%4,%5,%6,%7}, {%8,%9}, {%0,%1,%2,%3};"
                        : "+f"(acc[i][j][0]), "+f"(acc[i][j][1]),
                          "+f"(acc[i][j][2]), "+f"(acc[i][j][3])
                        : "r"(a[i][0]), "r"(a[i][1]), "r"(a[i][2]), "r"(a[i][3]),
                          "r"(b0), "r"(b1));
                }
            }
        }

        if ((g & 15) == 15) {
            // ---- per-tile epilogue ----
            int tile = bid + (g >> 4) * GRID_P;
            int rowBase = (tile >> 6) * BM;
            int colBase = (tile & 63) * BN;

            #pragma unroll
            for (int i = 0; i < 4; i++)
                #pragma unroll
                for (int j = 0; j < 4; j++)
                    #pragma unroll
                    for (int r = 0; r < 4; r++)
                        asm("ex2.approx.f32 %0, %0;" : "+f"(acc[i][j][r]));

            #pragma unroll
            for (int i = 0; i < 4; i++) {
                float r0 = 0.f, r1 = 0.f;
                #pragma unroll
                for (int j = 0; j < 4; j++) {
                    r0 += acc[i][j][0] + acc[i][j][1];
                    r1 += acc[i][j][2] + acc[i][j][3];
                }
                r0 += __shfl_xor_sync(0xffffffffu, r0, 1);
                r0 += __shfl_xor_sync(0xffffffffu, r0, 2);
                r1 += __shfl_xor_sync(0xffffffffu, r1, 1);
                r1 += __shfl_xor_sync(0xffffffffu, r1, 2);
                if ((lane & 3) == 0) {
                    int rbase = warpM * 64 + i * 16 + (lane >> 2);
                    atomicAdd(&rowsum_s[rbase], r0);
                    atomicAdd(&rowsum_s[rbase + 8], r1);
                }
            }
            #pragma unroll
            for (int j = 0; j < 4; j++) {
                float c0 = 0.f, c1 = 0.f;
                #pragma unroll
                for (int i = 0; i < 4; i++) {
                    c0 += acc[i][j][0] + acc[i][j][2];
                    c1 += acc[i][j][1] + acc[i][j][3];
                }
                c0 += __shfl_xor_sync(0xffffffffu, c0, 4);
                c0 += __shfl_xor_sync(0xffffffffu, c0, 8);
                c0 += __shfl_xor_sync(0xffffffffu, c0, 16);
                c1 += __shfl_xor_sync(0xffffffffu, c1, 4);
                c1 += __shfl_xor_sync(0xffffffffu, c1, 8);
                c1 += __shfl_xor_sync(0xffffffffu, c1, 16);
                if (lane < 4) {
                    int cbase = warpN * 32 + j * 8 + lane * 2;
                    atomicAdd(&colsum_s[cbase], c0);
                    atomicAdd(&colsum_s[cbase + 1], c1);
                }
            }

            __syncthreads();
            if (tid < BM) {
                atomicAdd(&g_rowsum[rowBase + tid], rowsum_s[tid]);
                rowsum_s[tid] = 0.f;
                atomicAdd(&g_colsum[colBase + tid], colsum_s[tid]);
                colsum_s[tid] = 0.f;
            }

            #pragma unroll
            for (int i = 0; i < 4; i++)
                #pragma unroll
                for (int j = 0; j < 4; j++)
                    #pragma unroll
                    for (int r = 0; r < 4; r++) acc[i][j][r] = 0.f;
        }
    }
}

// ---------------- 3) two-stage finalize ----------------
__global__ void partial_kernel() {
    int tid = threadIdx.x;
    int row = blockIdx.x * 256 + tid;
    float a = log2f(g_rowsum[row]) + log2f(g_colsum[row]);
    float d = g_diag[row];
    #pragma unroll
    for (int o = 16; o; o >>= 1) {
        a += __shfl_xor_sync(0xffffffffu, a, o);
        d += __shfl_xor_sync(0xffffffffu, d, o);
    }
    __shared__ float sa[8], sd[8];
    if ((tid & 31) == 0) { sa[tid >> 5] = a; sd[tid >> 5] = d; }
    __syncthreads();
    if (tid == 0) {
        float ta = 0.f, td = 0.f;
        #pragma unroll
        for (int i = 0; i < 8; i++) { ta += sa[i]; td += sd[i]; }
        g_parta[blockIdx.x] = ta;
        g_partd[blockIdx.x] = td;
    }
}

__global__ void final_kernel(float* __restrict__ out) {
    int lane = threadIdx.x;
    float a = g_parta[lane], d = g_partd[lane];
    #pragma unroll
    for (int o = 16; o; o >>= 1) {
        a += __shfl_xor_sync(0xffffffffu, a, o);
        d += __shfl_xor_sync(0xffffffffu, d, o);
    }
    if (lane == 0)
        out[0] = LN2F * (0.5f * a / (float)NROWS - d / (float)NROWS);
}

// ---------------- launch ----------------
extern "C" void kernel_launch(void* const* d_in, const int* in_sizes, int n_in,
                              void* d_out, int out_size) {
    const float* im  = (const float*)d_in[0];
    const float* cap = (const float*)d_in[1];
    float* out = (float*)d_out;

    cudaFuncSetAttribute(gemm_kernel, cudaFuncAttributeMaxDynamicSharedMemorySize, DYN_BYTES);

    prep_kernel<<<NROWS, 256>>>(im, cap);
    gemm_kernel<<<GRID_P, 256, DYN_BYTES>>>();
    partial_kernel<<<32, 256>>>();
    final_kernel<<<1, 32>>>(out);
}

// round 13
// speedup vs baseline: 1.0573x; 1.0573x over previous
#include <cuda_runtime.h>
#include <cuda_bf16.h>
#include <cstdint>

#define NROWS 8192
#define DIM   1024
#define SCALE_T 14.4269504088896341f   // (1/T)*log2(e)
#define LN2F 0.69314718055994531f

// ---------------- scratch ----------------
__device__ __nv_bfloat16 g_imn[(size_t)NROWS * DIM];   // normalized * SCALE_T
__device__ __nv_bfloat16 g_capn[(size_t)NROWS * DIM];  // normalized
__device__ float g_rowsum[NROWS];
__device__ float g_colsum[NROWS];
__device__ float g_diag[NROWS];                        // t_ii (exp2-domain logits)
__device__ float g_parta[32];
__device__ float g_partd[32];

// ---------------- helpers ----------------
__device__ __forceinline__ uint32_t smem_u32(const void* p) {
    uint32_t a;
    asm("{ .reg .u64 t; cvta.to.shared.u64 t, %1; cvt.u32.u64 %0, t; }" : "=r"(a) : "l"(p));
    return a;
}
__device__ __forceinline__ uint64_t gmem_u64(const void* p) {
    uint64_t a;
    asm("cvta.to.global.u64 %0, %1;" : "=l"(a) : "l"(p));
    return a;
}
__device__ __forceinline__ uint32_t elect_one() {
    uint32_t p;
    asm volatile("{ .reg .pred p; elect.sync _|p, 0xFFFFFFFF; selp.b32 %0, 1, 0, p; }" : "=r"(p));
    return p;
}
// passes when barrier's current phase bit != parity argument
__device__ __forceinline__ void mbar_wait(uint32_t a, uint32_t parity) {
    uint32_t done;
    asm volatile("{ .reg .pred p; mbarrier.try_wait.parity.acquire.cta.shared::cta.b64 p, [%1], %2; selp.b32 %0, 1, 0, p; }"
                 : "=r"(done) : "r"(a), "r"(parity) : "memory");
    if (!done) {
        asm volatile("{ .reg .pred P1; WL%=: mbarrier.try_wait.parity.acquire.cta.shared::cta.b64 P1, [%0], %1, 0x989680; @P1 bra.uni WD%=; bra.uni WL%=; WD%=: }"
                     :: "r"(a), "r"(parity) : "memory");
    }
}
#define SW128(o) ((o) ^ (((o) >> 3) & 0x70))

// ---------------- 1) prep: normalize both rows + diag + zero accumulators ----------------
__global__ void prep_kernel(const float* __restrict__ im,
                            const float* __restrict__ cap) {
    int row = blockIdx.x;
    int tid = threadIdx.x;
    const float4* a4 = reinterpret_cast<const float4*>(im + (size_t)row * DIM);
    const float4* b4 = reinterpret_cast<const float4*>(cap + (size_t)row * DIM);
    float4 va = a4[tid], vb = b4[tid];
    float sa = va.x * va.x + va.y * va.y + va.z * va.z + va.w * va.w;
    float sb = vb.x * vb.x + vb.y * vb.y + vb.z * vb.z + vb.w * vb.w;
    float sd = va.x * vb.x + va.y * vb.y + va.z * vb.z + va.w * vb.w;
    #pragma unroll
    for (int o = 16; o; o >>= 1) {
        sa += __shfl_xor_sync(0xffffffffu, sa, o);
        sb += __shfl_xor_sync(0xffffffffu, sb, o);
        sd += __shfl_xor_sync(0xffffffffu, sd, o);
    }
    __shared__ float wsa[8], wsb[8], wsd[8];
    if ((tid & 31) == 0) { wsa[tid >> 5] = sa; wsb[tid >> 5] = sb; wsd[tid >> 5] = sd; }
    __syncthreads();
    float ta = 0.f, tb = 0.f, td = 0.f;
    #pragma unroll
    for (int i = 0; i < 8; i++) { ta += wsa[i]; tb += wsb[i]; td += wsd[i]; }

    float ra = rsqrtf(ta), rb = rsqrtf(tb);
    float inva = ra * SCALE_T;
    __nv_bfloat162* dA = reinterpret_cast<__nv_bfloat162*>(g_imn + (size_t)row * DIM);
    __nv_bfloat162* dB = reinterpret_cast<__nv_bfloat162*>(g_capn + (size_t)row * DIM);
    dA[tid * 2 + 0] = __floats2bfloat162_rn(va.x * inva, va.y * inva);
    dA[tid * 2 + 1] = __floats2bfloat162_rn(va.z * inva, va.w * inva);
    dB[tid * 2 + 0] = __floats2bfloat162_rn(vb.x * rb, vb.y * rb);
    dB[tid * 2 + 1] = __floats2bfloat162_rn(vb.z * rb, vb.w * rb);

    if (tid == 0) {
        g_diag[row] = td * ra * rb * SCALE_T;
        g_rowsum[row] = 0.f;
        g_colsum[row] = 0.f;
    }
}

// ---------------- 2) persistent bf16 mma.sync GEMM, mbarrier async pipeline ----------------
// CTA tile 128x128, BK=64, 3-stage ring. 8 warps = 2(M) x 4(N), warp tile 64x32.
#define BM 128
#define BN 128
#define STAGE_BYTES 32768                 // A 16KB + B 16KB
#define DYN_BYTES (3 * STAGE_BYTES + 1024)
#define GRID_P 296                        // 2 CTA/SM * 148 SM
#define NTILES_TOTAL 4096                 // 64 x 64 tiles

extern __shared__ char dynsmem[];

__device__ __forceinline__ void issue_chunk(int g, int bid, uint32_t sbase,
                                            uint64_t gAbase, uint64_t gBbase, int tid) {
    int tile = bid + (g >> 4) * GRID_P;
    int rb = (tile >> 6) * BM;
    int cb = (tile & 63) * BN;
    uint32_t sStage = sbase + (uint32_t)(g % 3) * STAGE_BYTES;
    uint32_t k0b = (uint32_t)(g & 15) * 128;
    uint64_t gA = gAbase + (uint64_t)rb * (DIM * 2);
    uint64_t gB = gBbase + (uint64_t)cb * (DIM * 2);
    #pragma unroll
    for (int q = 0; q < 4; q++) {
        int chunk = tid + q * 256;
        int row = chunk >> 3, kc = chunk & 7;
        uint32_t soff = SW128(row * 128 + kc * 16);
        uint64_t goff = (uint64_t)row * (DIM * 2) + k0b + kc * 16;
        asm volatile("cp.async.cg.shared.global [%0], [%1], 16;"
                     :: "r"(sStage + soff), "l"(gA + goff) : "memory");
        asm volatile("cp.async.cg.shared.global [%0], [%1], 16;"
                     :: "r"(sStage + 16384 + soff), "l"(gB + goff) : "memory");
    }
}

__global__ void __launch_bounds__(256, 2) gemm_kernel() {
    const int tid = threadIdx.x, wid = tid >> 5, lane = tid & 31;
    const int warpM = wid >> 2;
    const int warpN = wid & 3;
    const int bid = blockIdx.x;
    const int ntiles = (NTILES_TOTAL - bid + (GRID_P - 1)) / GRID_P;
    const int totalChunks = ntiles * 16;

    __shared__ float rowsum_s[BM];
    __shared__ float colsum_s[BN];
    __shared__ __align__(8) uint64_t s_mbar[6];   // full[0..2], empty[0..2]
    if (tid < BM) { rowsum_s[tid] = 0.f; colsum_s[tid] = 0.f; }

    const uint32_t mb = smem_u32(s_mbar);
    if (tid == 0) {
        #pragma unroll
        for (int s = 0; s < 3; s++) {
            asm volatile("mbarrier.init.shared.b64 [%0], 256;" :: "r"(mb + s * 8) : "memory");
            asm volatile("mbarrier.init.shared.b64 [%0], 8;"   :: "r"(mb + 24 + s * 8) : "memory");
        }
    }
    __syncthreads();

    uint32_t raw = smem_u32(dynsmem);
    uint32_t sbase = (raw + 1023u) & ~1023u;

    const uint64_t gAbase = gmem_u64(g_imn);
    const uint64_t gBbase = gmem_u64(g_capn);

    // produce(g): wait empty (producer parity (i+1)&1), fill, arrive.NOINC on cp completion
    #define PRODUCE(gg) do {                                                   \
        int _g = (gg); int _s = _g % 3; int _i = _g / 3;                       \
        mbar_wait(mb + 24 + _s * 8, (uint32_t)((_i + 1) & 1));                 \
        issue_chunk(_g, bid, sbase, gAbase, gBbase, tid);                      \
        asm volatile("cp.async.mbarrier.arrive.noinc.shared.b64 [%0];"         \
                     :: "r"(mb + _s * 8) : "memory");                          \
    } while (0)

    PRODUCE(0);
    PRODUCE(1);

    float acc[4][4][4];
    #pragma unroll
    for (int i = 0; i < 4; i++)
        #pragma unroll
        for (int j = 0; j < 4; j++)
            #pragma unroll
            for (int r = 0; r < 4; r++) acc[i][j][r] = 0.f;

    // ldmatrix lane geometry
    const int laneRow = lane & 15;
    const uint32_t aXor = (uint32_t)((laneRow & 7) << 4);
    const uint32_t aHi  = (uint32_t)((lane >> 4) * 16);
    const int rowB0 = ((lane >> 4) & 1) * 8 + (lane & 7);
    const uint32_t bXor = (uint32_t)((lane & 7) << 4);
    const uint32_t bHi  = (uint32_t)(((lane >> 3) & 1) * 16);

    for (int g = 0; g < totalChunks; g++) {
        if (g + 2 < totalChunks) PRODUCE(g + 2);

        const int s = g % 3, gi = g / 3;
        mbar_wait(mb + s * 8, (uint32_t)(gi & 1));    // wait full[s] (consumer parity i&1)

        const uint32_t sA = sbase + (uint32_t)s * STAGE_BYTES;
        const uint32_t sB = sA + 16384;

        #pragma unroll
        for (int kk = 0; kk < 4; kk++) {
            uint32_t a[4][4], b[2][4];
            #pragma unroll
            for (int i = 0; i < 4; i++) {
                uint32_t addr = sA + (uint32_t)(warpM * 64 + i * 16 + laneRow) * 128
                              + (((uint32_t)kk * 32 + aHi) ^ aXor);
                asm volatile("ldmatrix.sync.aligned.m8n8.x4.shared.b16 {%0,%1,%2,%3}, [%4];"
                             : "=r"(a[i][0]), "=r"(a[i][1]), "=r"(a[i][2]), "=r"(a[i][3])
                             : "r"(addr));
            }
            #pragma unroll
            for (int jb = 0; jb < 2; jb++) {
                uint32_t addr = sB + (uint32_t)(warpN * 32 + jb * 16 + rowB0) * 128
                              + (((uint32_t)kk * 32 + bHi) ^ bXor);
                asm volatile("ldmatrix.sync.aligned.m8n8.x4.shared.b16 {%0,%1,%2,%3}, [%4];"
                             : "=r"(b[jb][0]), "=r"(b[jb][1]), "=r"(b[jb][2]), "=r"(b[jb][3])
                             : "r"(addr));
            }
            #pragma unroll
            for (int i = 0; i < 4; i++) {
                #pragma unroll
                for (int j = 0; j < 4; j++) {
                    uint32_t b0 = b[j >> 1][(j & 1) * 2];
                    uint32_t b1 = b[j >> 1][(j & 1) * 2 + 1];
                    asm volatile(
                        "mma.sync.aligned.m16n8k16.row.col.f32.bf16.bf16.f32 "
                        "{%0,%1,%2,%3}, {%4,%5,%6,%7}, {%8,%9}, {%0,%1,%2,%3};"
                        : "+f"(acc[i][j][0]), "+f"(acc[i][j][1]),
                          "+f"(acc[i][j][2]), "+f"(acc[i][j][3])
                        : "r"(a[i][0]), "r"(a[i][1]), "r"(a[i][2]), "r"(a[i][3]),
                          "r"(b0), "r"(b1));
                }
            }
        }

        // this warp is done reading stage s -> release it (1 arrive per warp, count=8)
        if (elect_one())
            asm volatile("mbarrier.arrive.shared.b64 _, [%0];"
                         :: "r"(mb + 24 + s * 8) : "memory");

        if ((g & 15) == 15) {
            // ---- per-tile epilogue ----
            int tile = bid + (g >> 4) * GRID_P;
            int rowBase = (tile >> 6) * BM;
            int colBase = (tile & 63) * BN;

            #pragma unroll
            for (int i = 0; i < 4; i++)
                #pragma unroll
                for (int j = 0; j < 4; j++)
                    #pragma unroll
                    for (int r = 0; r < 4; r++)
                        asm("ex2.approx.f32 %0, %0;" : "+f"(acc[i][j][r]));

            #pragma unroll
            for (int i = 0; i < 4; i++) {
                float r0 = 0.f, r1 = 0.f;
                #pragma unroll
                for (int j = 0; j < 4; j++) {
                    r0 += acc[i][j][0] + acc[i][j][1];
                    r1 += acc[i][j][2] + acc[i][j][3];
                }
                r0 += __shfl_xor_sync(0xffffffffu, r0, 1);
                r0 += __shfl_xor_sync(0xffffffffu, r0, 2);
                r1 += __shfl_xor_sync(0xffffffffu, r1, 1);
                r1 += __shfl_xor_sync(0xffffffffu, r1, 2);
                if ((lane & 3) == 0) {
                    int rbase = warpM * 64 + i * 16 + (lane >> 2);
                    atomicAdd(&rowsum_s[rbase], r0);
                    atomicAdd(&rowsum_s[rbase + 8], r1);
                }
            }
            #pragma unroll
            for (int j = 0; j < 4; j++) {
                float c0 = 0.f, c1 = 0.f;
                #pragma unroll
                for (int i = 0; i < 4; i++) {
                    c0 += acc[i][j][0] + acc[i][j][2];
                    c1 += acc[i][j][1] + acc[i][j][3];
                }
                c0 += __shfl_xor_sync(0xffffffffu, c0, 4);
                c0 += __shfl_xor_sync(0xffffffffu, c0, 8);
                c0 += __shfl_xor_sync(0xffffffffu, c0, 16);
                c1 += __shfl_xor_sync(0xffffffffu, c1, 4);
                c1 += __shfl_xor_sync(0xffffffffu, c1, 8);
                c1 += __shfl_xor_sync(0xffffffffu, c1, 16);
                if (lane < 4) {
                    int cbase = warpN * 32 + j * 8 + lane * 2;
                    atomicAdd(&colsum_s[cbase], c0);
                    atomicAdd(&colsum_s[cbase + 1], c1);
                }
            }

            __syncthreads();
            if (tid < BM) {
                atomicAdd(&g_rowsum[rowBase + tid], rowsum_s[tid]);
                rowsum_s[tid] = 0.f;
                atomicAdd(&g_colsum[colBase + tid], colsum_s[tid]);
                colsum_s[tid] = 0.f;
            }
            __syncthreads();

            #pragma unroll
            for (int i = 0; i < 4; i++)
                #pragma unroll
                for (int j = 0; j < 4; j++)
                    #pragma unroll
                    for (int r = 0; r < 4; r++) acc[i][j][r] = 0.f;
        }
    }
    #undef PRODUCE
}

// ---------------- 3) two-stage finalize ----------------
__global__ void partial_kernel() {
    int tid = threadIdx.x;
    int row = blockIdx.x * 256 + tid;
    float a = log2f(g_rowsum[row]) + log2f(g_colsum[row]);
    float d = g_diag[row];
    #pragma unroll
    for (int o = 16; o; o >>= 1) {
        a += __shfl_xor_sync(0xffffffffu, a, o);
        d += __shfl_xor_sync(0xffffffffu, d, o);
    }
    __shared__ float sa[8], sd[8];
    if ((tid & 31) == 0) { sa[tid >> 5] = a; sd[tid >> 5] = d; }
    __syncthreads();
    if (tid == 0) {
        float ta = 0.f, td = 0.f;
        #pragma unroll
        for (int i = 0; i < 8; i++) { ta += sa[i]; td += sd[i]; }
        g_parta[blockIdx.x] = ta;
        g_partd[blockIdx.x] = td;
    }
}

__global__ void final_kernel(float* __restrict__ out) {
    int lane = threadIdx.x;
    float a = g_parta[lane], d = g_partd[lane];
    #pragma unroll
    for (int o = 16; o; o >>= 1) {
        a += __shfl_xor_sync(0xffffffffu, a, o);
        d += __shfl_xor_sync(0xffffffffu, d, o);
    }
    if (lane == 0)
        out[0] = LN2F * (0.5f * a / (float)NROWS - d / (float)NROWS);
}

// ---------------- launch ----------------
extern "C" void kernel_launch(void* const* d_in, const int* in_sizes, int n_in,
                              void* d_out, int out_size) {
    const float* im  = (const float*)d_in[0];
    const float* cap = (const float*)d_in[1];
    float* out = (float*)d_out;

    cudaFuncSetAttribute(gemm_kernel, cudaFuncAttributeMaxDynamicSharedMemorySize, DYN_BYTES);

    prep_kernel<<<NROWS, 256>>>(im, cap);
    gemm_kernel<<<GRID_P, 256, DYN_BYTES>>>();
    partial_kernel<<<32, 256>>>();
    final_kernel<<<1, 32>>>(out);
}

// round 14
// speedup vs baseline: 1.0686x; 1.0107x over previous
#include <cuda_runtime.h>
#include <cuda_bf16.h>
#include <cstdint>

#define NROWS 8192
#define DIM   1024
#define SCALE_T 14.4269504088896341f   // (1/T)*log2(e)
#define LN2F 0.69314718055994531f

// ---------------- scratch ----------------
__device__ __nv_bfloat16 g_imn[(size_t)NROWS * DIM];   // normalized * SCALE_T
__device__ __nv_bfloat16 g_capn[(size_t)NROWS * DIM];  // normalized
__device__ float g_rowsum[NROWS];
__device__ float g_colsum[NROWS];
__device__ float g_diag[NROWS];                        // t_ii (exp2-domain logits)
__device__ float g_parta[32];
__device__ float g_partd[32];

// ---------------- helpers ----------------
__device__ __forceinline__ uint32_t smem_u32(const void* p) {
    uint32_t a;
    asm("{ .reg .u64 t; cvta.to.shared.u64 t, %1; cvt.u32.u64 %0, t; }" : "=r"(a) : "l"(p));
    return a;
}
__device__ __forceinline__ uint64_t gmem_u64(const void* p) {
    uint64_t a;
    asm("cvta.to.global.u64 %0, %1;" : "=l"(a) : "l"(p));
    return a;
}
__device__ __forceinline__ uint32_t elect_one() {
    uint32_t p;
    asm volatile("{ .reg .pred p; elect.sync _|p, 0xFFFFFFFF; selp.b32 %0, 1, 0, p; }" : "=r"(p));
    return p;
}
// passes when barrier's current phase bit != parity argument
__device__ __forceinline__ void mbar_wait(uint32_t a, uint32_t parity) {
    uint32_t done;
    asm volatile("{ .reg .pred p; mbarrier.try_wait.parity.acquire.cta.shared::cta.b64 p, [%1], %2; selp.b32 %0, 1, 0, p; }"
                 : "=r"(done) : "r"(a), "r"(parity) : "memory");
    if (!done) {
        asm volatile("{ .reg .pred P1; WL%=: mbarrier.try_wait.parity.acquire.cta.shared::cta.b64 P1, [%0], %1, 0x989680; @P1 bra.uni WD%=; bra.uni WL%=; WD%=: }"
                     :: "r"(a), "r"(parity) : "memory");
    }
}
#define SW128(o) ((o) ^ (((o) >> 3) & 0x70))

// ---------------- 1) prep: normalize both rows + diag + zero accumulators ----------------
__global__ void prep_kernel(const float* __restrict__ im,
                            const float* __restrict__ cap) {
    int row = blockIdx.x;
    int tid = threadIdx.x;
    const float4* a4 = reinterpret_cast<const float4*>(im + (size_t)row * DIM);
    const float4* b4 = reinterpret_cast<const float4*>(cap + (size_t)row * DIM);
    float4 va = a4[tid], vb = b4[tid];
    float sa = va.x * va.x + va.y * va.y + va.z * va.z + va.w * va.w;
    float sb = vb.x * vb.x + vb.y * vb.y + vb.z * vb.z + vb.w * vb.w;
    float sd = va.x * vb.x + va.y * vb.y + va.z * vb.z + va.w * vb.w;
    #pragma unroll
    for (int o = 16; o; o >>= 1) {
        sa += __shfl_xor_sync(0xffffffffu, sa, o);
        sb += __shfl_xor_sync(0xffffffffu, sb, o);
        sd += __shfl_xor_sync(0xffffffffu, sd, o);
    }
    __shared__ float wsa[8], wsb[8], wsd[8];
    if ((tid & 31) == 0) { wsa[tid >> 5] = sa; wsb[tid >> 5] = sb; wsd[tid >> 5] = sd; }
    __syncthreads();
    float ta = 0.f, tb = 0.f, td = 0.f;
    #pragma unroll
    for (int i = 0; i < 8; i++) { ta += wsa[i]; tb += wsb[i]; td += wsd[i]; }

    float ra = rsqrtf(ta), rb = rsqrtf(tb);
    float inva = ra * SCALE_T;
    __nv_bfloat162* dA = reinterpret_cast<__nv_bfloat162*>(g_imn + (size_t)row * DIM);
    __nv_bfloat162* dB = reinterpret_cast<__nv_bfloat162*>(g_capn + (size_t)row * DIM);
    dA[tid * 2 + 0] = __floats2bfloat162_rn(va.x * inva, va.y * inva);
    dA[tid * 2 + 1] = __floats2bfloat162_rn(va.z * inva, va.w * inva);
    dB[tid * 2 + 0] = __floats2bfloat162_rn(vb.x * rb, vb.y * rb);
    dB[tid * 2 + 1] = __floats2bfloat162_rn(vb.z * rb, vb.w * rb);

    if (tid == 0) {
        g_diag[row] = td * ra * rb * SCALE_T;
        g_rowsum[row] = 0.f;
        g_colsum[row] = 0.f;
    }
}

// ---------------- 2) persistent bf16 mma.sync GEMM, mbarrier pipeline ----------------
// CTA tile 128x128, BK=64, 3-stage ring. 4 warps = 2(M) x 2(N), warp tile 64x64.
// 128 threads/CTA, 2 CTA/SM -> 256-reg budget/thread (fragment-prefetch headroom).
#define BM 128
#define BN 128
#define STAGE_BYTES 32768                 // A 16KB + B 16KB
#define DYN_BYTES (3 * STAGE_BYTES + 1024)
#define GRID_P 296                        // 2 CTA/SM * 148 SM
#define NTILES_TOTAL 4096                 // 64 x 64 tiles

extern __shared__ char dynsmem[];

__device__ __forceinline__ void issue_chunk(int g, int bid, uint32_t sbase,
                                            uint64_t gAbase, uint64_t gBbase, int tid) {
    int tile = bid + (g >> 4) * GRID_P;
    int rb = (tile >> 6) * BM;
    int cb = (tile & 63) * BN;
    uint32_t sStage = sbase + (uint32_t)(g % 3) * STAGE_BYTES;
    uint32_t k0b = (uint32_t)(g & 15) * 128;
    uint64_t gA = gAbase + (uint64_t)rb * (DIM * 2);
    uint64_t gB = gBbase + (uint64_t)cb * (DIM * 2);
    #pragma unroll
    for (int q = 0; q < 8; q++) {
        int chunk = tid + q * 128;
        int row = chunk >> 3, kc = chunk & 7;
        uint32_t soff = SW128(row * 128 + kc * 16);
        uint64_t goff = (uint64_t)row * (DIM * 2) + k0b + kc * 16;
        asm volatile("cp.async.cg.shared.global [%0], [%1], 16;"
                     :: "r"(sStage + soff), "l"(gA + goff) : "memory");
        asm volatile("cp.async.cg.shared.global [%0], [%1], 16;"
                     :: "r"(sStage + 16384 + soff), "l"(gB + goff) : "memory");
    }
}

__global__ void __launch_bounds__(128, 2) gemm_kernel() {
    const int tid = threadIdx.x, wid = tid >> 5, lane = tid & 31;
    const int warpM = wid >> 1;           // 0..1 -> 64-row slab
    const int warpN = wid & 1;            // 0..1 -> 64-col slab
    const int bid = blockIdx.x;
    const int ntiles = (NTILES_TOTAL - bid + (GRID_P - 1)) / GRID_P;
    const int totalChunks = ntiles * 16;

    __shared__ float rowsum_s[BM];
    __shared__ float colsum_s[BN];
    __shared__ __align__(8) uint64_t s_mbar[6];   // full[0..2], empty[0..2]
    rowsum_s[tid] = 0.f;
    colsum_s[tid] = 0.f;

    const uint32_t mb = smem_u32(s_mbar);
    if (tid == 0) {
        #pragma unroll
        for (int s = 0; s < 3; s++) {
            asm volatile("mbarrier.init.shared.b64 [%0], 128;" :: "r"(mb + s * 8) : "memory");
            asm volatile("mbarrier.init.shared.b64 [%0], 4;"   :: "r"(mb + 24 + s * 8) : "memory");
        }
    }
    __syncthreads();

    uint32_t raw = smem_u32(dynsmem);
    uint32_t sbase = (raw + 1023u) & ~1023u;

    const uint64_t gAbase = gmem_u64(g_imn);
    const uint64_t gBbase = gmem_u64(g_capn);

    // produce(g): wait empty (producer parity (i+1)&1), fill, arrive.NOINC on cp completion
    #define PRODUCE(gg) do {                                                   \
        int _g = (gg); int _s = _g % 3; int _i = _g / 3;                       \
        mbar_wait(mb + 24 + _s * 8, (uint32_t)((_i + 1) & 1));                 \
        issue_chunk(_g, bid, sbase, gAbase, gBbase, tid);                      \
        asm volatile("cp.async.mbarrier.arrive.noinc.shared.b64 [%0];"         \
                     :: "r"(mb + _s * 8) : "memory");                          \
    } while (0)

    PRODUCE(0);
    PRODUCE(1);

    float acc[4][8][4];
    #pragma unroll
    for (int i = 0; i < 4; i++)
        #pragma unroll
        for (int j = 0; j < 8; j++)
            #pragma unroll
            for (int r = 0; r < 4; r++) acc[i][j][r] = 0.f;

    // ldmatrix lane geometry
    const int laneRow = lane & 15;
    const uint32_t aXor = (uint32_t)((laneRow & 7) << 4);
    const uint32_t aHi  = (uint32_t)((lane >> 4) * 16);
    const int rowB0 = ((lane >> 4) & 1) * 8 + (lane & 7);
    const uint32_t bXor = (uint32_t)((lane & 7) << 4);
    const uint32_t bHi  = (uint32_t)(((lane >> 3) & 1) * 16);

    for (int g = 0; g < totalChunks; g++) {
        if (g + 2 < totalChunks) PRODUCE(g + 2);

        const int s = g % 3, gi = g / 3;
        mbar_wait(mb + s * 8, (uint32_t)(gi & 1));    // wait full[s]

        const uint32_t sA = sbase + (uint32_t)s * STAGE_BYTES;
        const uint32_t sB = sA + 16384;

        #pragma unroll
        for (int kk = 0; kk < 4; kk++) {
            uint32_t a[4][4], b[4][4];
            #pragma unroll
            for (int i = 0; i < 4; i++) {
                uint32_t addr = sA + (uint32_t)(warpM * 64 + i * 16 + laneRow) * 128
                              + (((uint32_t)kk * 32 + aHi) ^ aXor);
                asm volatile("ldmatrix.sync.aligned.m8n8.x4.shared.b16 {%0,%1,%2,%3}, [%4];"
                             : "=r"(a[i][0]), "=r"(a[i][1]), "=r"(a[i][2]), "=r"(a[i][3])
                             : "r"(addr));
            }
            #pragma unroll
            for (int jb = 0; jb < 4; jb++) {
                uint32_t addr = sB + (uint32_t)(warpN * 64 + jb * 16 + rowB0) * 128
                              + (((uint32_t)kk * 32 + bHi) ^ bXor);
                asm volatile("ldmatrix.sync.aligned.m8n8.x4.shared.b16 {%0,%1,%2,%3}, [%4];"
                             : "=r"(b[jb][0]), "=r"(b[jb][1]), "=r"(b[jb][2]), "=r"(b[jb][3])
                             : "r"(addr));
            }
            #pragma unroll
            for (int i = 0; i < 4; i++) {
                #pragma unroll
                for (int j = 0; j < 8; j++) {
                    uint32_t b0 = b[j >> 1][(j & 1) * 2];
                    uint32_t b1 = b[j >> 1][(j & 1) * 2 + 1];
                    asm volatile(
                        "mma.sync.aligned.m16n8k16.row.col.f32.bf16.bf16.f32 "
                        "{%0,%1,%2,%3}, {%4,%5,%6,%7}, {%8,%9}, {%0,%1,%2,%3};"
                        : "+f"(acc[i][j][0]), "+f"(acc[i][j][1]),
                          "+f"(acc[i][j][2]), "+f"(acc[i][j][3])
                        : "r"(a[i][0]), "r"(a[i][1]), "r"(a[i][2]), "r"(a[i][3]),
                          "r"(b0), "r"(b1));
                }
            }
        }

        // this warp is done reading stage s -> release it (1 arrive per warp, count=4)
        if (elect_one())
            asm volatile("mbarrier.arrive.shared.b64 _, [%0];"
                         :: "r"(mb + 24 + s * 8) : "memory");

        if ((g & 15) == 15) {
            // ---- per-tile epilogue ----
            int tile = bid + (g >> 4) * GRID_P;
            int rowBase = (tile >> 6) * BM;
            int colBase = (tile & 63) * BN;

            #pragma unroll
            for (int i = 0; i < 4; i++)
                #pragma unroll
                for (int j = 0; j < 8; j++)
                    #pragma unroll
                    for (int r = 0; r < 4; r++)
                        asm("ex2.approx.f32 %0, %0;" : "+f"(acc[i][j][r]));

            #pragma unroll
            for (int i = 0; i < 4; i++) {
                float r0 = 0.f, r1 = 0.f;
                #pragma unroll
                for (int j = 0; j < 8; j++) {
                    r0 += acc[i][j][0] + acc[i][j][1];
                    r1 += acc[i][j][2] + acc[i][j][3];
                }
                r0 += __shfl_xor_sync(0xffffffffu, r0, 1);
                r0 += __shfl_xor_sync(0xffffffffu, r0, 2);
                r1 += __shfl_xor_sync(0xffffffffu, r1, 1);
                r1 += __shfl_xor_sync(0xffffffffu, r1, 2);
                if ((lane & 3) == 0) {
                    int rbase = warpM * 64 + i * 16 + (lane >> 2);
                    atomicAdd(&rowsum_s[rbase], r0);
                    atomicAdd(&rowsum_s[rbase + 8], r1);
                }
            }
            #pragma unroll
            for (int j = 0; j < 8; j++) {
                float c0 = 0.f, c1 = 0.f;
                #pragma unroll
                for (int i = 0; i < 4; i++) {
                    c0 += acc[i][j][0] + acc[i][j][2];
                    c1 += acc[i][j][1] + acc[i][j][3];
                }
                c0 += __shfl_xor_sync(0xffffffffu, c0, 4);
                c0 += __shfl_xor_sync(0xffffffffu, c0, 8);
                c0 += __shfl_xor_sync(0xffffffffu, c0, 16);
                c1 += __shfl_xor_sync(0xffffffffu, c1, 4);
                c1 += __shfl_xor_sync(0xffffffffu, c1, 8);
                c1 += __shfl_xor_sync(0xffffffffu, c1, 16);
                if (lane < 4) {
                    int cbase = warpN * 64 + j * 8 + lane * 2;
                    atomicAdd(&colsum_s[cbase], c0);
                    atomicAdd(&colsum_s[cbase + 1], c1);
                }
            }

            __syncthreads();
            atomicAdd(&g_rowsum[rowBase + tid], rowsum_s[tid]);
            rowsum_s[tid] = 0.f;
            atomicAdd(&g_colsum[colBase + tid], colsum_s[tid]);
            colsum_s[tid] = 0.f;
            __syncthreads();

            #pragma unroll
            for (int i = 0; i < 4; i++)
                #pragma unroll
                for (int j = 0; j < 8; j++)
                    #pragma unroll
                    for (int r = 0; r < 4; r++) acc[i][j][r] = 0.f;
        }
    }
    #undef PRODUCE
}

// ---------------- 3) two-stage finalize ----------------
__global__ void partial_kernel() {
    int tid = threadIdx.x;
    int row = blockIdx.x * 256 + tid;
    float a = log2f(g_rowsum[row]) + log2f(g_colsum[row]);
    float d = g_diag[row];
    #pragma unroll
    for (int o = 16; o; o >>= 1) {
        a += __shfl_xor_sync(0xffffffffu, a, o);
        d += __shfl_xor_sync(0xffffffffu, d, o);
    }
    __shared__ float sa[8], sd[8];
    if ((tid & 31) == 0) { sa[tid >> 5] = a; sd[tid >> 5] = d; }
    __syncthreads();
    if (tid == 0) {
        float ta = 0.f, td = 0.f;
        #pragma unroll
        for (int i = 0; i < 8; i++) { ta += sa[i]; td += sd[i]; }
        g_parta[blockIdx.x] = ta;
        g_partd[blockIdx.x] = td;
    }
}

__global__ void final_kernel(float* __restrict__ out) {
    int lane = threadIdx.x;
    float a = g_parta[lane], d = g_partd[lane];
    #pragma unroll
    for (int o = 16; o; o >>= 1) {
        a += __shfl_xor_sync(0xffffffffu, a, o);
        d += __shfl_xor_sync(0xffffffffu, d, o);
    }
    if (lane == 0)
        out[0] = LN2F * (0.5f * a / (float)NROWS - d / (float)NROWS);
}

// ---------------- launch ----------------
extern "C" void kernel_launch(void* const* d_in, const int* in_sizes, int n_in,
                              void* d_out, int out_size) {
    const float* im  = (const float*)d_in[0];
    const float* cap = (const float*)d_in[1];
    float* out = (float*)d_out;

    cudaFuncSetAttribute(gemm_kernel, cudaFuncAttributeMaxDynamicSharedMemorySize, DYN_BYTES);

    prep_kernel<<<NROWS, 256>>>(im, cap);
    gemm_kernel<<<GRID_P, 128, DYN_BYTES>>>();
    partial_kernel<<<32, 256>>>();
    final_kernel<<<1, 32>>>(out);
}

// round 17
// speedup vs baseline: 1.0973x; 1.0268x over previous
#include <cuda_runtime.h>
#include <cuda_bf16.h>
#include <cstdint>

#define NROWS 8192
#define DIM   1024
#define SCALE_T 14.4269504088896341f   // (1/T)*log2(e)
#define LN2F 0.69314718055994531f

// ---------------- scratch ----------------
__device__ __nv_bfloat16 g_imn[(size_t)NROWS * DIM];   // normalized * SCALE_T
__device__ __nv_bfloat16 g_capn[(size_t)NROWS * DIM];  // normalized
__device__ float g_rowsum[NROWS];
__device__ float g_colsum[NROWS];
__device__ float g_diag[NROWS];                        // t_ii (exp2-domain logits)
__device__ float g_parta[32];
__device__ float g_partd[32];

// ---------------- helpers ----------------
__device__ __forceinline__ uint32_t smem_u32(const void* p) {
    uint32_t a;
    asm("{ .reg .u64 t; cvta.to.shared.u64 t, %1; cvt.u32.u64 %0, t; }" : "=r"(a) : "l"(p));
    return a;
}
__device__ __forceinline__ uint64_t gmem_u64(const void* p) {
    uint64_t a;
    asm("cvta.to.global.u64 %0, %1;" : "=l"(a) : "l"(p));
    return a;
}
__device__ __forceinline__ uint32_t elect_one() {
    uint32_t p;
    asm volatile("{ .reg .pred p; elect.sync _|p, 0xFFFFFFFF; selp.b32 %0, 1, 0, p; }" : "=r"(p));
    return p;
}
// passes when barrier's current phase bit != parity argument
__device__ __forceinline__ void mbar_wait(uint32_t a, uint32_t parity) {
    uint32_t done;
    asm volatile("{ .reg .pred p; mbarrier.try_wait.parity.acquire.cta.shared::cta.b64 p, [%1], %2; selp.b32 %0, 1, 0, p; }"
                 : "=r"(done) : "r"(a), "r"(parity) : "memory");
    if (!done) {
        asm volatile("{ .reg .pred P1; WL%=: mbarrier.try_wait.parity.acquire.cta.shared::cta.b64 P1, [%0], %1, 0x989680; @P1 bra.uni WD%=; bra.uni WL%=; WD%=: }"
                     :: "r"(a), "r"(parity) : "memory");
    }
}
#define SW128(o) ((o) ^ (((o) >> 3) & 0x70))

// ---------------- 1) prep: normalize both rows + diag + zero accumulators ----------------
__global__ void prep_kernel(const float* __restrict__ im,
                            const float* __restrict__ cap) {
    int row = blockIdx.x;
    int tid = threadIdx.x;
    const float4* a4 = reinterpret_cast<const float4*>(im + (size_t)row * DIM);
    const float4* b4 = reinterpret_cast<const float4*>(cap + (size_t)row * DIM);
    float4 va = a4[tid], vb = b4[tid];
    float sa = va.x * va.x + va.y * va.y + va.z * va.z + va.w * va.w;
    float sb = vb.x * vb.x + vb.y * vb.y + vb.z * vb.z + vb.w * vb.w;
    float sd = va.x * vb.x + va.y * vb.y + va.z * vb.z + va.w * vb.w;
    #pragma unroll
    for (int o = 16; o; o >>= 1) {
        sa += __shfl_xor_sync(0xffffffffu, sa, o);
        sb += __shfl_xor_sync(0xffffffffu, sb, o);
        sd += __shfl_xor_sync(0xffffffffu, sd, o);
    }
    __shared__ float wsa[8], wsb[8], wsd[8];
    if ((tid & 31) == 0) { wsa[tid >> 5] = sa; wsb[tid >> 5] = sb; wsd[tid >> 5] = sd; }
    __syncthreads();
    float ta = 0.f, tb = 0.f, td = 0.f;
    #pragma unroll
    for (int i = 0; i < 8; i++) { ta += wsa[i]; tb += wsb[i]; td += wsd[i]; }

    float ra = rsqrtf(ta), rb = rsqrtf(tb);
    float inva = ra * SCALE_T;
    __nv_bfloat162* dA = reinterpret_cast<__nv_bfloat162*>(g_imn + (size_t)row * DIM);
    __nv_bfloat162* dB = reinterpret_cast<__nv_bfloat162*>(g_capn + (size_t)row * DIM);
    dA[tid * 2 + 0] = __floats2bfloat162_rn(va.x * inva, va.y * inva);
    dA[tid * 2 + 1] = __floats2bfloat162_rn(va.z * inva, va.w * inva);
    dB[tid * 2 + 0] = __floats2bfloat162_rn(vb.x * rb, vb.y * rb);
    dB[tid * 2 + 1] = __floats2bfloat162_rn(vb.z * rb, vb.w * rb);

    if (tid == 0) {
        g_diag[row] = td * ra * rb * SCALE_T;
        g_rowsum[row] = 0.f;
        g_colsum[row] = 0.f;
    }
}

// ---------------- 2) persistent bf16 mma.sync GEMM, mbarrier pipeline ----------------
// CTA tile 128x128, BK=64, 3-stage ring. 4 warps = 2(M) x 2(N), warp tile 64x64.
// Fragment double-buffering across kk: LDSM for kk+1 issued before MMAs of kk.
#define BM 128
#define BN 128
#define STAGE_BYTES 32768                 // A 16KB + B 16KB
#define DYN_BYTES (3 * STAGE_BYTES + 1024)
#define GRID_P 296                        // 2 CTA/SM * 148 SM
#define NTILES_TOTAL 4096                 // 64 x 64 tiles

extern __shared__ char dynsmem[];

__device__ __forceinline__ void issue_chunk(int g, int bid, uint32_t sbase,
                                            uint64_t gAbase, uint64_t gBbase, int tid) {
    int tile = bid + (g >> 4) * GRID_P;
    int rb = (tile >> 6) * BM;
    int cb = (tile & 63) * BN;
    uint32_t sStage = sbase + (uint32_t)(g % 3) * STAGE_BYTES;
    uint32_t k0b = (uint32_t)(g & 15) * 128;
    uint64_t gA = gAbase + (uint64_t)rb * (DIM * 2);
    uint64_t gB = gBbase + (uint64_t)cb * (DIM * 2);
    #pragma unroll
    for (int q = 0; q < 8; q++) {
        int chunk = tid + q * 128;
        int row = chunk >> 3, kc = chunk & 7;
        uint32_t soff = SW128(row * 128 + kc * 16);
        uint64_t goff = (uint64_t)row * (DIM * 2) + k0b + kc * 16;
        asm volatile("cp.async.cg.shared.global [%0], [%1], 16;"
                     :: "r"(sStage + soff), "l"(gA + goff) : "memory");
        asm volatile("cp.async.cg.shared.global [%0], [%1], 16;"
                     :: "r"(sStage + 16384 + soff), "l"(gB + goff) : "memory");
    }
}

// load A/B fragments for one kk into buffers aF/bF
__device__ __forceinline__ void load_frags(uint32_t aF[4][4], uint32_t bF[4][4],
                                           uint32_t sA, uint32_t sB, int kk,
                                           int warpM, int warpN, int laneRow, int rowB0,
                                           uint32_t aXor, uint32_t aHi,
                                           uint32_t bXor, uint32_t bHi) {
    #pragma unroll
    for (int i = 0; i < 4; i++) {
        uint32_t addr = sA + (uint32_t)(warpM * 64 + i * 16 + laneRow) * 128
                      + (((uint32_t)kk * 32 + aHi) ^ aXor);
        asm volatile("ldmatrix.sync.aligned.m8n8.x4.shared.b16 {%0,%1,%2,%3}, [%4];"
                     : "=r"(aF[i][0]), "=r"(aF[i][1]), "=r"(aF[i][2]), "=r"(aF[i][3])
                     : "r"(addr));
    }
    #pragma unroll
    for (int jb = 0; jb < 4; jb++) {
        uint32_t addr = sB + (uint32_t)(warpN * 64 + jb * 16 + rowB0) * 128
                      + (((uint32_t)kk * 32 + bHi) ^ bXor);
        asm volatile("ldmatrix.sync.aligned.m8n8.x4.shared.b16 {%0,%1,%2,%3}, [%4];"
                     : "=r"(bF[jb][0]), "=r"(bF[jb][1]), "=r"(bF[jb][2]), "=r"(bF[jb][3])
                     : "r"(addr));
    }
}

__global__ void __launch_bounds__(128, 2) gemm_kernel() {
    const int tid = threadIdx.x, wid = tid >> 5, lane = tid & 31;
    const int warpM = wid >> 1;           // 0..1 -> 64-row slab
    const int warpN = wid & 1;            // 0..1 -> 64-col slab
    const int bid = blockIdx.x;
    const int ntiles = (NTILES_TOTAL - bid + (GRID_P - 1)) / GRID_P;
    const int totalChunks = ntiles * 16;

    __shared__ float rowsum_s[BM];
    __shared__ float colsum_s[BN];
    __shared__ __align__(8) uint64_t s_mbar[6];   // full[0..2], empty[0..2]
    rowsum_s[tid] = 0.f;
    colsum_s[tid] = 0.f;

    const uint32_t mb = smem_u32(s_mbar);
    if (tid == 0) {
        #pragma unroll
        for (int s = 0; s < 3; s++) {
            asm volatile("mbarrier.init.shared.b64 [%0], 128;" :: "r"(mb + s * 8) : "memory");
            asm volatile("mbarrier.init.shared.b64 [%0], 4;"   :: "r"(mb + 24 + s * 8) : "memory");
        }
    }
    __syncthreads();

    uint32_t raw = smem_u32(dynsmem);
    uint32_t sbase = (raw + 1023u) & ~1023u;

    const uint64_t gAbase = gmem_u64(g_imn);
    const uint64_t gBbase = gmem_u64(g_capn);

    #define PRODUCE(gg) do {                                                   \
        int _g = (gg); int _s = _g % 3; int _i = _g / 3;                       \
        mbar_wait(mb + 24 + _s * 8, (uint32_t)((_i + 1) & 1));                 \
        issue_chunk(_g, bid, sbase, gAbase, gBbase, tid);                      \
        asm volatile("cp.async.mbarrier.arrive.noinc.shared.b64 [%0];"         \
                     :: "r"(mb + _s * 8) : "memory");                          \
    } while (0)

    PRODUCE(0);
    PRODUCE(1);

    float acc[4][8][4];
    #pragma unroll
    for (int i = 0; i < 4; i++)
        #pragma unroll
        for (int j = 0; j < 8; j++)
            #pragma unroll
            for (int r = 0; r < 4; r++) acc[i][j][r] = 0.f;

    // ldmatrix lane geometry
    const int laneRow = lane & 15;
    const uint32_t aXor = (uint32_t)((laneRow & 7) << 4);
    const uint32_t aHi  = (uint32_t)((lane >> 4) * 16);
    const int rowB0 = ((lane >> 4) & 1) * 8 + (lane & 7);
    const uint32_t bXor = (uint32_t)((lane & 7) << 4);
    const uint32_t bHi  = (uint32_t)(((lane >> 3) & 1) * 16);

    uint32_t a[2][4][4], b[2][4][4];

    for (int g = 0; g < totalChunks; g++) {
        if (g + 2 < totalChunks) PRODUCE(g + 2);

        const int s = g % 3, gi = g / 3;
        mbar_wait(mb + s * 8, (uint32_t)(gi & 1));    // wait full[s]

        const uint32_t sA = sbase + (uint32_t)s * STAGE_BYTES;
        const uint32_t sB = sA + 16384;

        load_frags(a[0], b[0], sA, sB, 0,
                   warpM, warpN, laneRow, rowB0, aXor, aHi, bXor, bHi);

        #pragma unroll
        for (int kk = 0; kk < 4; kk++) {
            const int cur = kk & 1;
            if (kk < 3)
                load_frags(a[(kk + 1) & 1], b[(kk + 1) & 1], sA, sB, kk + 1,
                           warpM, warpN, laneRow, rowB0, aXor, aHi, bXor, bHi);
            #pragma unroll
            for (int i = 0; i < 4; i++) {
                #pragma unroll
                for (int j = 0; j < 8; j++) {
                    uint32_t b0 = b[cur][j >> 1][(j & 1) * 2];
                    uint32_t b1 = b[cur][j >> 1][(j & 1) * 2 + 1];
                    asm volatile(
                        "mma.sync.aligned.m16n8k16.row.col.f32.bf16.bf16.f32 "
                        "{%0,%1,%2,%3}, {%4,%5,%6,%7}, {%8,%9}, {%0,%1,%2,%3};"
                        : "+f"(acc[i][j][0]), "+f"(acc[i][j][1]),
                          "+f"(acc[i][j][2]), "+f"(acc[i][j][3])
                        : "r"(a[cur][i][0]), "r"(a[cur][i][1]),
                          "r"(a[cur][i][2]), "r"(a[cur][i][3]),
                          "r"(b0), "r"(b1));
                }
            }
        }

        // this warp done reading stage s -> release (1 arrive per warp, count=4)
        if (elect_one())
            asm volatile("mbarrier.arrive.shared.b64 _, [%0];"
                         :: "r"(mb + 24 + s * 8) : "memory");

        if ((g & 15) == 15) {
            // ---- per-tile epilogue ----
            int tile = bid + (g >> 4) * GRID_P;
            int rowBase = (tile >> 6) * BM;
            int colBase = (tile & 63) * BN;

            #pragma unroll
            for (int i = 0; i < 4; i++)
                #pragma unroll
                for (int j = 0; j < 8; j++)
                    #pragma unroll
                    for (int r = 0; r < 4; r++)
                        asm("ex2.approx.f32 %0, %0;" : "+f"(acc[i][j][r]));

            #pragma unroll
            for (int i = 0; i < 4; i++) {
                float r0 = 0.f, r1 = 0.f;
                #pragma unroll
                for (int j = 0; j < 8; j++) {
                    r0 += acc[i][j][0] + acc[i][j][1];
                    r1 += acc[i][j][2] + acc[i][j][3];
                }
                r0 += __shfl_xor_sync(0xffffffffu, r0, 1);
                r0 += __shfl_xor_sync(0xffffffffu, r0, 2);
                r1 += __shfl_xor_sync(0xffffffffu, r1, 1);
                r1 += __shfl_xor_sync(0xffffffffu, r1, 2);
                if ((lane & 3) == 0) {
                    int rbase = warpM * 64 + i * 16 + (lane >> 2);
                    atomicAdd(&rowsum_s[rbase], r0);
                    atomicAdd(&rowsum_s[rbase + 8], r1);
                }
            }
            #pragma unroll
            for (int j = 0; j < 8; j++) {
                float c0 = 0.f, c1 = 0.f;
                #pragma unroll
                for (int i = 0; i < 4; i++) {
                    c0 += acc[i][j][0] + acc[i][j][2];
                    c1 += acc[i][j][1] + acc[i][j][3];
                }
                c0 += __shfl_xor_sync(0xffffffffu, c0, 4);
                c0 += __shfl_xor_sync(0xffffffffu, c0, 8);
                c0 += __shfl_xor_sync(0xffffffffu, c0, 16);
                c1 += __shfl_xor_sync(0xffffffffu, c1, 4);
                c1 += __shfl_xor_sync(0xffffffffu, c1, 8);
                c1 += __shfl_xor_sync(0xffffffffu, c1, 16);
                if (lane < 4) {
                    int cbase = warpN * 64 + j * 8 + lane * 2;
                    atomicAdd(&colsum_s[cbase], c0);
                    atomicAdd(&colsum_s[cbase + 1], c1);
                }
            }

            __syncthreads();
            atomicAdd(&g_rowsum[rowBase + tid], rowsum_s[tid]);
            rowsum_s[tid] = 0.f;
            atomicAdd(&g_colsum[colBase + tid], colsum_s[tid]);
            colsum_s[tid] = 0.f;
            __syncthreads();

            #pragma unroll
            for (int i = 0; i < 4; i++)
                #pragma unroll
                for (int j = 0; j < 8; j++)
                    #pragma unroll
                    for (int r = 0; r < 4; r++) acc[i][j][r] = 0.f;
        }
    }
    #undef PRODUCE
}

// ---------------- 3) two-stage finalize ----------------
__global__ void partial_kernel() {
    int tid = threadIdx.x;
    int row = blockIdx.x * 256 + tid;
    float a = log2f(g_rowsum[row]) + log2f(g_colsum[row]);
    float d = g_diag[row];
    #pragma unroll
    for (int o = 16; o; o >>= 1) {
        a += __shfl_xor_sync(0xffffffffu, a, o);
        d += __shfl_xor_sync(0xffffffffu, d, o);
    }
    __shared__ float sa[8], sd[8];
    if ((tid & 31) == 0) { sa[tid >> 5] = a; sd[tid >> 5] = d; }
    __syncthreads();
    if (tid == 0) {
        float ta = 0.f, td = 0.f;
        #pragma unroll
        for (int i = 0; i < 8; i++) { ta += sa[i]; td += sd[i]; }
        g_parta[blockIdx.x] = ta;
        g_partd[blockIdx.x] = td;
    }
}

__global__ void final_kernel(float* __restrict__ out) {
    int lane = threadIdx.x;
    float a = g_parta[lane], d = g_partd[lane];
    #pragma unroll
    for (int o = 16; o; o >>= 1) {
        a += __shfl_xor_sync(0xffffffffu, a, o);
        d += __shfl_xor_sync(0xffffffffu, d, o);
    }
    if (lane == 0)
        out[0] = LN2F * (0.5f * a / (float)NROWS - d / (float)NROWS);
}

// ---------------- launch ----------------
extern "C" void kernel_launch(void* const* d_in, const int* in_sizes, int n_in,
                              void* d_out, int out_size) {
    const float* im  = (const float*)d_in[0];
    const float* cap = (const float*)d_in[1];
    float* out = (float*)d_out;

    cudaFuncSetAttribute(gemm_kernel, cudaFuncAttributeMaxDynamicSharedMemorySize, DYN_BYTES);

    prep_kernel<<<NROWS, 256>>>(im, cap);
    gemm_kernel<<<GRID_P, 128, DYN_BYTES>>>();
    partial_kernel<<<32, 256>>>();
    final_kernel<<<1, 32>>>(out);
}